// round 2
// baseline (speedup 1.0000x reference)
#include <cuda_runtime.h>
#include <stdint.h>

// Problem constants
#define B        8
#define D        256          // 16x16 score grid
#define NSAMP    500
#define KTOP     10
#define HS       16
#define SCALE    64
#define PATCH    128
#define IMGH     1024
#define IMGW     1024
#define PATCH_ELEMS (B * KTOP * 3 * PATCH * PATCH)  // 3,932,160

// ------------------------- scratch (static, no allocs) -------------------------
__device__ float g_norm[B * D];
__device__ int   g_count[B * KTOP * D];
__device__ int   g_nzcnt[B * KTOP];
__device__ int   g_nzcell[B * KTOP * D];
__device__ float g_nzw[B * KTOP * D];

// ------------------------- threefry2x32 (JAX key(1) = {0,1}) -------------------
__device__ __forceinline__ uint32_t rotl32(uint32_t v, int r) {
    return (v << r) | (v >> (32 - r));
}
__device__ __forceinline__ void tf_round(uint32_t& x0, uint32_t& x1, int r) {
    x0 += x1; x1 = rotl32(x1, r); x1 ^= x0;
}
__device__ __forceinline__ void threefry2x32(uint32_t c0, uint32_t c1,
                                             uint32_t& o0, uint32_t& o1) {
    const uint32_t ks0 = 0u, ks1 = 1u, ks2 = 0x1BD11BDAu ^ ks0 ^ ks1;
    uint32_t x0 = c0 + ks0, x1 = c1 + ks1;
    tf_round(x0, x1, 13); tf_round(x0, x1, 15); tf_round(x0, x1, 26); tf_round(x0, x1, 6);
    x0 += ks1; x1 += ks2 + 1u;
    tf_round(x0, x1, 17); tf_round(x0, x1, 29); tf_round(x0, x1, 16); tf_round(x0, x1, 24);
    x0 += ks2; x1 += ks0 + 2u;
    tf_round(x0, x1, 13); tf_round(x0, x1, 15); tf_round(x0, x1, 26); tf_round(x0, x1, 6);
    x0 += ks0; x1 += ks1 + 3u;
    tf_round(x0, x1, 17); tf_round(x0, x1, 29); tf_round(x0, x1, 16); tf_round(x0, x1, 24);
    x0 += ks1; x1 += ks2 + 4u;
    tf_round(x0, x1, 13); tf_round(x0, x1, 15); tf_round(x0, x1, 26); tf_round(x0, x1, 6);
    x0 += ks2; x1 += ks0 + 5u;
    o0 = x0; o1 = x1;
}

// XLA ErfInv32 (Giles) — exact coefficients XLA emits for lax.erf_inv on f32
__device__ __forceinline__ float erfinv_xla(float x) {
    float w = -log1pf(-__fmul_rn(x, x));
    float p;
    if (w < 5.0f) {
        w = w - 2.5f;
        p = 2.81022636e-08f;
        p = fmaf(p, w, 3.43273939e-07f);
        p = fmaf(p, w, -3.5233877e-06f);
        p = fmaf(p, w, -4.39150654e-06f);
        p = fmaf(p, w, 0.00021858087f);
        p = fmaf(p, w, -0.00125372503f);
        p = fmaf(p, w, -0.00417768164f);
        p = fmaf(p, w, 0.246640727f);
        p = fmaf(p, w, 1.50140941f);
    } else {
        w = sqrtf(w) - 3.0f;
        p = -0.000200214257f;
        p = fmaf(p, w, 0.000100950558f);
        p = fmaf(p, w, 0.00134934322f);
        p = fmaf(p, w, -0.00367342844f);
        p = fmaf(p, w, 0.00573950773f);
        p = fmaf(p, w, -0.0076224613f);
        p = fmaf(p, w, 0.00943887047f);
        p = fmaf(p, w, 1.00167406f);
        p = fmaf(p, w, 2.83297682f);
    }
    return __fmul_rn(p, x);
}

// noise[e] exactly as jax.random.normal(key(1), (8,500,256), f32) with
// jax_threefry_partitionable=True (modern JAX default):
//   counter = (hi32(e), lo32(e)) = (0, e);  bits = o0 ^ o1
__device__ __forceinline__ float jax_normal(uint32_t e) {
    uint32_t o0, o1;
    threefry2x32(0u, e, o0, o1);
    uint32_t bits = o0 ^ o1;
    float u = __uint_as_float((bits >> 9) | 0x3f800000u) - 1.0f;  // [0,1)
    const float lo = -0.99999994f;            // nextafter(-1,0) in f32
    const float span = 2.0f;                  // f32(1.0 - lo) rounds to 2.0 (ties-to-even)
    float v = fmaxf(lo, __fadd_rn(__fmul_rn(u, span), lo));
    return __fmul_rn(1.41421354f /* f32(sqrt(2)) */, erfinv_xla(v));
}

// ------------------------- kernel 1: entropy + normalize + zero counts ---------
__global__ void k1_prep(const float* __restrict__ scores, float* __restrict__ entr_out) {
    int tid = threadIdx.x;
    // zero the rank-count scratch
    for (int i = tid; i < B * KTOP * D; i += 256) g_count[i] = 0;

    int w = tid >> 5;        // warp = batch
    int lane = tid & 31;
    const float* s = scores + w * D;

    float v[8];
    float mx = -3.0e38f, mn = 3.0e38f;
    #pragma unroll
    for (int q = 0; q < 8; q++) {
        v[q] = s[lane + q * 32];
        mx = fmaxf(mx, v[q]);
        mn = fminf(mn, v[q]);
    }
    #pragma unroll
    for (int o = 16; o; o >>= 1) {
        mx = fmaxf(mx, __shfl_xor_sync(0xffffffffu, mx, o));
        mn = fminf(mn, __shfl_xor_sync(0xffffffffu, mn, o));
    }
    float sumexp = 0.f;
    #pragma unroll
    for (int q = 0; q < 8; q++) sumexp += expf(v[q] - mx);
    #pragma unroll
    for (int o = 16; o; o >>= 1) sumexp += __shfl_xor_sync(0xffffffffu, sumexp, o);
    float lse = mx + logf(sumexp);

    float ent = 0.f;
    #pragma unroll
    for (int q = 0; q < 8; q++) {
        float lp = v[q] - lse;
        ent += expf(lp) * (-lp);
    }
    #pragma unroll
    for (int o = 16; o; o >>= 1) ent += __shfl_xor_sync(0xffffffffu, ent, o);

    float denom = (mx - mn) + 1e-05f;
    #pragma unroll
    for (int q = 0; q < 8; q++)
        g_norm[w * D + lane + q * 32] = __fdiv_rn(v[q] - mn, denom);

    __shared__ float sh_ent[8];
    if (lane == 0) sh_ent[w] = ent;
    __syncthreads();
    if (tid == 0) {
        float e = 0.f;
        #pragma unroll
        for (int i = 0; i < 8; i++) e += sh_ent[i];
        *entr_out = e * (1.0f / 8.0f);
    }
}

// ------------------------- kernel 2: per-sample top-10 + rank histogram --------
__global__ void k2_topk() {
    int bs = blockIdx.x;            // b*500 + s
    int b = bs / NSAMP;
    int j = threadIdx.x;            // 0..255 (grid cell)
    int lane = j & 31, wid = j >> 5;

    uint32_t e = (uint32_t)bs * D + j;
    float noise = jax_normal(e);
    float pert = __fadd_rn(g_norm[b * D + j], __fmul_rn(noise, 0.05f));

    // orderable key: (value asc-mapped) << 8 | (255 - j)  -> max = largest value, ties -> lowest index
    uint32_t fb = __float_as_uint(pert);
    uint32_t ordv = fb ^ ((fb & 0x80000000u) ? 0xFFFFFFFFu : 0x80000000u);
    unsigned long long key = ((unsigned long long)ordv << 8) | (unsigned long long)(255 - j);

    __shared__ unsigned long long wmax[8];
    __shared__ int topidx[KTOP];

    for (int t = 0; t < KTOP; t++) {
        unsigned long long k = key;
        #pragma unroll
        for (int o = 16; o; o >>= 1) {
            unsigned long long other = __shfl_down_sync(0xffffffffu, k, o);
            if (other > k) k = other;
        }
        if (lane == 0) wmax[wid] = k;
        __syncthreads();
        if (j == 0) {
            unsigned long long m = wmax[0];
            #pragma unroll
            for (int i = 1; i < 8; i++) if (wmax[i] > m) m = wmax[i];
            topidx[t] = 255 - (int)(m & 0xFFull);
        }
        __syncthreads();
        if (j == topidx[t]) key = 0ull;   // remove winner
    }

    if (j == 0) {
        // sort the 10 winning indices ascending (rank k = k-th smallest)
        int a[KTOP];
        #pragma unroll
        for (int i = 0; i < KTOP; i++) a[i] = topidx[i];
        #pragma unroll
        for (int i = 1; i < KTOP; i++) {
            int x = a[i], q = i - 1;
            while (q >= 0 && a[q] > x) { a[q + 1] = a[q]; q--; }
            a[q + 1] = x;
        }
        #pragma unroll
        for (int t = 0; t < KTOP; t++)
            atomicAdd(&g_count[(b * KTOP + t) * D + a[t]], 1);
    }
}

// ------------------------- kernel 3: compact nonzero weights -------------------
__global__ void k3_compact() {
    int bk = blockIdx.x;            // 0..79
    __shared__ int cnt;
    if (threadIdx.x == 0) cnt = 0;
    __syncthreads();
    int c = g_count[bk * D + threadIdx.x];
    if (c > 0) {
        int p = atomicAdd(&cnt, 1);
        g_nzcell[bk * D + p] = threadIdx.x;
        g_nzw[bk * D + p] = (float)c / 500.0f;
    }
    __syncthreads();
    if (threadIdx.x == 0) g_nzcnt[bk] = cnt;
}

// ------------------------- kernel 4: sparse patch gather -----------------------
__global__ void k4_patches(const float* __restrict__ x, float* __restrict__ out) {
    int bk = blockIdx.x;            // b*10 + k
    int b = bk / KTOP;
    int cz = blockIdx.y;            // c*4 + rowtile
    int c = cz >> 2, tile = cz & 3;

    __shared__ int   scell[D];
    __shared__ float swt[D];
    int nnz = g_nzcnt[bk];
    if (threadIdx.x < nnz) {
        scell[threadIdx.x] = g_nzcell[bk * D + threadIdx.x];
        swt[threadIdx.x]   = g_nzw[bk * D + threadIdx.x];
    }
    __syncthreads();

    const float* plane = x + ((size_t)(b * 3 + c) << 20);   // 1024*1024 per plane
    float* obase = out + ((size_t)(bk * 3 + c) << 14);      // 128*128 per (b,k,c)

    int wq = threadIdx.x & 127;
    int r0 = threadIdx.x >> 7;      // 0 or 1

    for (int it = 0; it < 16; ++it) {
        int h = tile * 32 + it * 2 + r0;
        float acc = 0.f;
        for (int m = 0; m < nnz; ++m) {
            int cell = scell[m];
            int rr = (cell >> 4) * SCALE + h - 32;
            int cc = (cell & 15) * SCALE + wq - 32;
            if ((unsigned)rr < (unsigned)IMGH && (unsigned)cc < (unsigned)IMGW)
                acc = fmaf(swt[m], plane[rr * IMGW + cc], acc);
        }
        obase[h * PATCH + wq] = acc;
    }
}

// ------------------------- launch ----------------------------------------------
extern "C" void kernel_launch(void* const* d_in, const int* in_sizes, int n_in,
                              void* d_out, int out_size) {
    const float* x_high = (const float*)d_in[0];
    const float* scores = (const float*)d_in[1];
    // robustness: pick by size (x_high has 25,165,824 elems, scores 2,048)
    if (n_in >= 2 && in_sizes[0] < in_sizes[1]) {
        x_high = (const float*)d_in[1];
        scores = (const float*)d_in[0];
    }
    float* out = (float*)d_out;
    float* entr_out = out + (out_size > PATCH_ELEMS ? PATCH_ELEMS : out_size - 1);

    k1_prep<<<1, 256>>>(scores, entr_out);
    k2_topk<<<B * NSAMP, 256>>>();
    k3_compact<<<B * KTOP, 256>>>();
    dim3 g4(B * KTOP, 12);
    k4_patches<<<g4, 256>>>(x_high, out);
}

// round 3
// speedup vs baseline: 2.5063x; 2.5063x over previous
#include <cuda_runtime.h>
#include <stdint.h>

// Problem constants
#define B        8
#define D        256          // 16x16 score grid
#define NSAMP    500
#define KTOP     10
#define SCALE    64
#define PATCH    128
#define IMGH     1024
#define IMGW     1024
#define PATCH_ELEMS (B * KTOP * 3 * PATCH * PATCH)  // 3,932,160

// ------------------------- scratch (static, no allocs) -------------------------
__device__ float g_norm[B * D];
__device__ int   g_count[B * KTOP * D];
__device__ int   g_nzcnt[B * KTOP];
__device__ int2  g_nzcw[B * KTOP * D];   // {packed (rowbase<<16 | colbase&0xFFFF), weight bits}

// ------------------------- threefry2x32 (JAX key(1) = {0,1}) -------------------
__device__ __forceinline__ uint32_t rotl32(uint32_t v, int r) {
    return (v << r) | (v >> (32 - r));
}
__device__ __forceinline__ void tf_round(uint32_t& x0, uint32_t& x1, int r) {
    x0 += x1; x1 = rotl32(x1, r); x1 ^= x0;
}
__device__ __forceinline__ void threefry2x32(uint32_t c0, uint32_t c1,
                                             uint32_t& o0, uint32_t& o1) {
    const uint32_t ks0 = 0u, ks1 = 1u, ks2 = 0x1BD11BDAu ^ ks0 ^ ks1;
    uint32_t x0 = c0 + ks0, x1 = c1 + ks1;
    tf_round(x0, x1, 13); tf_round(x0, x1, 15); tf_round(x0, x1, 26); tf_round(x0, x1, 6);
    x0 += ks1; x1 += ks2 + 1u;
    tf_round(x0, x1, 17); tf_round(x0, x1, 29); tf_round(x0, x1, 16); tf_round(x0, x1, 24);
    x0 += ks2; x1 += ks0 + 2u;
    tf_round(x0, x1, 13); tf_round(x0, x1, 15); tf_round(x0, x1, 26); tf_round(x0, x1, 6);
    x0 += ks0; x1 += ks1 + 3u;
    tf_round(x0, x1, 17); tf_round(x0, x1, 29); tf_round(x0, x1, 16); tf_round(x0, x1, 24);
    x0 += ks1; x1 += ks2 + 4u;
    tf_round(x0, x1, 13); tf_round(x0, x1, 15); tf_round(x0, x1, 26); tf_round(x0, x1, 6);
    x0 += ks2; x1 += ks0 + 5u;
    o0 = x0; o1 = x1;
}

// XLA ErfInv32 (Giles) — exact coefficients XLA emits for lax.erf_inv on f32
__device__ __forceinline__ float erfinv_xla(float x) {
    float w = -log1pf(-__fmul_rn(x, x));
    float p;
    if (w < 5.0f) {
        w = w - 2.5f;
        p = 2.81022636e-08f;
        p = fmaf(p, w, 3.43273939e-07f);
        p = fmaf(p, w, -3.5233877e-06f);
        p = fmaf(p, w, -4.39150654e-06f);
        p = fmaf(p, w, 0.00021858087f);
        p = fmaf(p, w, -0.00125372503f);
        p = fmaf(p, w, -0.00417768164f);
        p = fmaf(p, w, 0.246640727f);
        p = fmaf(p, w, 1.50140941f);
    } else {
        w = sqrtf(w) - 3.0f;
        p = -0.000200214257f;
        p = fmaf(p, w, 0.000100950558f);
        p = fmaf(p, w, 0.00134934322f);
        p = fmaf(p, w, -0.00367342844f);
        p = fmaf(p, w, 0.00573950773f);
        p = fmaf(p, w, -0.0076224613f);
        p = fmaf(p, w, 0.00943887047f);
        p = fmaf(p, w, 1.00167406f);
        p = fmaf(p, w, 2.83297682f);
    }
    return __fmul_rn(p, x);
}

// noise[e] exactly as jax.random.normal(key(1), (8,500,256), f32) with
// jax_threefry_partitionable=True: counter=(0,e), bits = o0 ^ o1
__device__ __forceinline__ float jax_normal(uint32_t e) {
    uint32_t o0, o1;
    threefry2x32(0u, e, o0, o1);
    uint32_t bits = o0 ^ o1;
    float u = __uint_as_float((bits >> 9) | 0x3f800000u) - 1.0f;  // [0,1)
    const float lo = -0.99999994f;            // nextafter(-1,0) in f32
    const float span = 2.0f;                  // f32(1.0 - lo)
    float v = fmaxf(lo, __fadd_rn(__fmul_rn(u, span), lo));
    return __fmul_rn(1.41421354f /* f32(sqrt(2)) */, erfinv_xla(v));
}

// ------------------------- kernel 1: entropy + normalize + zero counts ---------
__global__ void k1_prep(const float* __restrict__ scores, float* __restrict__ entr_out) {
    int tid = threadIdx.x;
    for (int i = tid; i < B * KTOP * D; i += 256) g_count[i] = 0;

    int w = tid >> 5;        // warp = batch
    int lane = tid & 31;
    const float* s = scores + w * D;

    float v[8];
    float mx = -3.0e38f, mn = 3.0e38f;
    #pragma unroll
    for (int q = 0; q < 8; q++) {
        v[q] = s[lane + q * 32];
        mx = fmaxf(mx, v[q]);
        mn = fminf(mn, v[q]);
    }
    #pragma unroll
    for (int o = 16; o; o >>= 1) {
        mx = fmaxf(mx, __shfl_xor_sync(0xffffffffu, mx, o));
        mn = fminf(mn, __shfl_xor_sync(0xffffffffu, mn, o));
    }
    float sumexp = 0.f;
    #pragma unroll
    for (int q = 0; q < 8; q++) sumexp += expf(v[q] - mx);
    #pragma unroll
    for (int o = 16; o; o >>= 1) sumexp += __shfl_xor_sync(0xffffffffu, sumexp, o);
    float lse = mx + logf(sumexp);

    float ent = 0.f;
    #pragma unroll
    for (int q = 0; q < 8; q++) {
        float lp = v[q] - lse;
        ent += expf(lp) * (-lp);
    }
    #pragma unroll
    for (int o = 16; o; o >>= 1) ent += __shfl_xor_sync(0xffffffffu, ent, o);

    float denom = (mx - mn) + 1e-05f;
    #pragma unroll
    for (int q = 0; q < 8; q++)
        g_norm[w * D + lane + q * 32] = __fdiv_rn(v[q] - mn, denom);

    __shared__ float sh_ent[8];
    if (lane == 0) sh_ent[w] = ent;
    __syncthreads();
    if (tid == 0) {
        float e = 0.f;
        #pragma unroll
        for (int i = 0; i < 8; i++) e += sh_ent[i];
        *entr_out = e * (1.0f / 8.0f);
    }
}

// ------------------------- kernel 2: warp-per-sample top-10 --------------------
// 500 blocks x 256 threads; each warp handles one sample, no barriers.
#define SWAPD(i, j) { if (key[i] < key[j]) { unsigned long long t = key[i]; key[i] = key[j]; key[j] = t; } }

__global__ void k2_topk() {
    int wid = threadIdx.x >> 5, lane = threadIdx.x & 31;
    int bs = blockIdx.x * 8 + wid;          // 0..3999
    int b = bs / NSAMP;

    unsigned long long key[8];
    #pragma unroll
    for (int q = 0; q < 8; q++) {
        int j = q * 32 + lane;
        float noise = jax_normal((uint32_t)bs * D + (uint32_t)j);
        float pert = __fadd_rn(g_norm[b * D + j], __fmul_rn(noise, 0.05f));
        uint32_t fb = __float_as_uint(pert);
        uint32_t ordv = fb ^ ((fb & 0x80000000u) ? 0xFFFFFFFFu : 0x80000000u);
        key[q] = ((unsigned long long)ordv << 8) | (unsigned long long)(255 - j);
    }

    // sort key[0..7] descending (19-comparator network)
    SWAPD(0,1) SWAPD(2,3) SWAPD(4,5) SWAPD(6,7)
    SWAPD(0,2) SWAPD(1,3) SWAPD(4,6) SWAPD(5,7)
    SWAPD(1,2) SWAPD(5,6)
    SWAPD(0,4) SWAPD(1,5) SWAPD(2,6) SWAPD(3,7)
    SWAPD(2,4) SWAPD(3,5)
    SWAPD(1,2) SWAPD(3,4) SWAPD(5,6)

    int a[KTOP];
    #pragma unroll
    for (int t = 0; t < KTOP; t++) {
        unsigned long long m = key[0];
        #pragma unroll
        for (int o = 16; o; o >>= 1) {
            unsigned long long other = __shfl_xor_sync(0xffffffffu, m, o);
            if (other > m) m = other;
        }
        a[t] = 255 - (int)(m & 0xFFull);
        if (key[0] == m) {          // exactly one lane: pop my head
            #pragma unroll
            for (int i = 0; i < 7; i++) key[i] = key[i + 1];
            key[7] = 0ull;
        }
    }

    // sort the 10 indices ascending (same data in all lanes)
    #pragma unroll
    for (int i = 1; i < KTOP; i++) {
        #pragma unroll
        for (int q2 = KTOP - 1; q2 >= 1; q2--) {
            if (q2 <= i && a[q2] < a[q2 - 1]) { int t = a[q2]; a[q2] = a[q2 - 1]; a[q2 - 1] = t; }
        }
    }

    int mine = a[0];
    #pragma unroll
    for (int t = 1; t < KTOP; t++) if (lane == t) mine = a[t];
    if (lane < KTOP)
        atomicAdd(&g_count[(b * KTOP + lane) * D + mine], 1);
}

// ------------------------- kernel 3: compact nonzero weights -------------------
__global__ void k3_compact() {
    int bk = blockIdx.x;            // 0..79
    __shared__ int cnt;
    if (threadIdx.x == 0) cnt = 0;
    __syncthreads();
    int c = g_count[bk * D + threadIdx.x];
    if (c > 0) {
        int p = atomicAdd(&cnt, 1);
        int cell = threadIdx.x;
        int rowb = (cell >> 4) * SCALE - 32;           // [-32, 928]
        int colb = (cell & 15) * SCALE - 32;           // [-32, 928]
        g_nzcw[bk * D + p] = make_int2((rowb << 16) | (colb & 0xFFFF),
                                       __float_as_int((float)c / 500.0f));
    }
    __syncthreads();
    if (threadIdx.x == 0) g_nzcnt[bk] = cnt;
}

// ------------------------- kernel 4: sparse patch gather (float4, 4-row) -------
// grid (80, 12): x = b*10+k, y = c*4 + rowtile(32 rows)
// block 256: lane group wq4 = tid&31 -> 4 w-pixels; r = tid>>5 -> rows r+{0,8,16,24}
__global__ void k4_patches(const float* __restrict__ x, float* __restrict__ out) {
    int bk = blockIdx.x;
    int b = bk / KTOP;
    int cz = blockIdx.y;
    int c = cz >> 2, tile = cz & 3;

    __shared__ int2 scw[D];
    int nnz = g_nzcnt[bk];
    if (threadIdx.x < nnz)
        scw[threadIdx.x] = g_nzcw[bk * D + threadIdx.x];
    __syncthreads();

    const float* plane = x + ((size_t)(b * 3 + c) << 20);   // 1024*1024 per plane
    float* obase = out + ((size_t)(bk * 3 + c) << 14);      // 128*128 per (b,k,c)

    int w0 = (threadIdx.x & 31) * 4;        // 0..124
    int hbase = tile * 32 + (threadIdx.x >> 5);

    float4 acc0 = make_float4(0.f, 0.f, 0.f, 0.f);
    float4 acc1 = acc0, acc2 = acc0, acc3 = acc0;

    for (int m = 0; m < nnz; ++m) {
        int2 cw = scw[m];
        int rowb = cw.x >> 16;
        int colb = (cw.x << 16) >> 16;       // sign-extended
        float wt = __int_as_float(cw.y);
        int cc = colb + w0;
        bool vc = (unsigned)cc < (unsigned)IMGW;   // whole 4-chunk in/out (proved)
        int rr0 = rowb + hbase;
        #pragma unroll
        for (int hh = 0; hh < 4; hh++) {
            int rr = rr0 + hh * 8;
            if (vc && (unsigned)rr < (unsigned)IMGH) {
                float4 v = *reinterpret_cast<const float4*>(plane + rr * IMGW + cc);
                float4& acc = (hh == 0) ? acc0 : (hh == 1) ? acc1 : (hh == 2) ? acc2 : acc3;
                acc.x = fmaf(wt, v.x, acc.x);
                acc.y = fmaf(wt, v.y, acc.y);
                acc.z = fmaf(wt, v.z, acc.z);
                acc.w = fmaf(wt, v.w, acc.w);
            }
        }
    }

    #pragma unroll
    for (int hh = 0; hh < 4; hh++) {
        int h = hbase + hh * 8;
        float4 acc = (hh == 0) ? acc0 : (hh == 1) ? acc1 : (hh == 2) ? acc2 : acc3;
        *reinterpret_cast<float4*>(obase + h * PATCH + w0) = acc;
    }
}

// ------------------------- launch ----------------------------------------------
extern "C" void kernel_launch(void* const* d_in, const int* in_sizes, int n_in,
                              void* d_out, int out_size) {
    const float* x_high = (const float*)d_in[0];
    const float* scores = (const float*)d_in[1];
    if (n_in >= 2 && in_sizes[0] < in_sizes[1]) {
        x_high = (const float*)d_in[1];
        scores = (const float*)d_in[0];
    }
    float* out = (float*)d_out;
    float* entr_out = out + (out_size > PATCH_ELEMS ? PATCH_ELEMS : out_size - 1);

    k1_prep<<<1, 256>>>(scores, entr_out);
    k2_topk<<<NSAMP, 256>>>();              // 500 blocks, warp-per-sample
    k3_compact<<<B * KTOP, 256>>>();
    dim3 g4(B * KTOP, 12);
    k4_patches<<<g4, 256>>>(x_high, out);
}